// round 10
// baseline (speedup 1.0000x reference)
#include <cuda_runtime.h>
#include <cuda_fp16.h>
#include <stdint.h>

#define B_TOK 8192
#define DIM   2048
#define NEXP  8

#define BM 128
#define BN 256
#define BK 128
#define NKC (DIM / BK)          // 16
#define NNT (DIM / BN)          // 8
#define MAXTILES 72
#define NCW 16                  // compute warps
#define GTHREADS (NCW * 32 + 64)   // + 2 converter warps = 576

#define TILE_A 32768            // 128m x 128k fp16, 2 k-subtiles of 16KB, SW128
#define TILE_B 65536            // 128k x 256n fp16, 4 n-subtiles of 16KB, SW128
#define STAGE_SZ (TILE_A + TILE_B)
#define OFF_B TILE_A
#define OFF_MB (2 * STAGE_SZ)        // 196608
#define OFF_ROWS (OFF_MB + 64)
#define OFF_SE (OFF_ROWS + 512)
#define SMEM_REQ (OFF_SE + 512 + 1024)

#define NTB 32

// -------- device scratch --------
__device__ int d_bh[NTB][NEXP];
__device__ int d_boff[NTB][NEXP];
__device__ int d_poff[NEXP + 1];
__device__ int d_is64 = 1;           // monotone latch (input-fixed -> deterministic)
__device__ int d_done = 0;
__device__ int d_perm[MAXTILES * 128];

__device__ volatile int f_a[MAXTILES * NKC];        // 0=unclaimed 1=claimed 2=done
__device__ volatile int f_b[NEXP * NNT * NKC];
__device__ volatile int f_scat;

__device__ __align__(128) char g_xa[(size_t)MAXTILES * NKC * TILE_A];
__device__ __align__(128) char g_wb[(size_t)NEXP * NNT * NKC * TILE_B];

// ======================= helpers =======================
__device__ __forceinline__ uint32_t smem_u32(const void* p) {
    uint32_t a;
    asm("{ .reg .u64 t; cvta.to.shared.u64 t, %1; cvt.u32.u64 %0, t; }" : "=r"(a) : "l"(p));
    return a;
}
__device__ __forceinline__ uint32_t sw128(uint32_t off) { return off ^ ((off >> 3) & 0x70); }

__device__ __forceinline__ void ldsm_x4(uint32_t* r, uint32_t addr) {
    asm volatile("ldmatrix.sync.aligned.m8n8.x4.shared.b16 {%0,%1,%2,%3}, [%4];"
                 : "=r"(r[0]), "=r"(r[1]), "=r"(r[2]), "=r"(r[3]) : "r"(addr));
}
__device__ __forceinline__ void ldsm_x4_t(uint32_t* r, uint32_t addr) {
    asm volatile("ldmatrix.sync.aligned.m8n8.x4.trans.shared.b16 {%0,%1,%2,%3}, [%4];"
                 : "=r"(r[0]), "=r"(r[1]), "=r"(r[2]), "=r"(r[3]) : "r"(addr));
}
__device__ __forceinline__ void mma16816(float* d, const uint32_t* a, uint32_t b0, uint32_t b1) {
    asm volatile(
        "mma.sync.aligned.m16n8k16.row.col.f32.f16.f16.f32 "
        "{%0,%1,%2,%3}, {%4,%5,%6,%7}, {%8,%9}, {%0,%1,%2,%3};"
        : "+f"(d[0]), "+f"(d[1]), "+f"(d[2]), "+f"(d[3])
        : "r"(a[0]), "r"(a[1]), "r"(a[2]), "r"(a[3]), "r"(b0), "r"(b1));
}
__device__ __forceinline__ void bulk_g2s(uint32_t dst, const void* src, uint32_t bytes, uint32_t mbar) {
    asm volatile(
        "{\n\t.reg .u64 g;\n\tcvta.to.global.u64 g, %1;\n\t"
        "cp.async.bulk.shared::cluster.global.mbarrier::complete_tx::bytes [%0], [g], %2, [%3];\n\t}"
        :: "r"(dst), "l"(src), "r"(bytes), "r"(mbar) : "memory");
}
#define MBARRIER_INIT(addr, cnt) \
    asm volatile("mbarrier.init.shared.b64 [%0], %1;" :: "r"((uint32_t)(addr)), "r"((uint32_t)(cnt)) : "memory")
#define MBARRIER_EXPECT_TX(addr, tx) \
    asm volatile("mbarrier.arrive.expect_tx.shared.b64 _, [%0], %1;" :: "r"((uint32_t)(addr)), "r"((uint32_t)(tx)) : "memory")
#define MBARRIER_WAIT_PARITY(addr, par) do { \
    uint32_t _m = (uint32_t)(addr); uint32_t _p = (uint32_t)(par); uint32_t _done; \
    asm volatile("{\n\t.reg .pred p;\n\t" \
        "mbarrier.try_wait.parity.acquire.cta.shared::cta.b64 p, [%1], %2;\n\t" \
        "selp.b32 %0, 1, 0, p;\n\t}" : "=r"(_done) : "r"(_m), "r"(_p) : "memory"); \
    if (!_done) { \
        asm volatile("{\n\t.reg .pred P1;\n\t" \
            "WL_%=:\n\tmbarrier.try_wait.parity.acquire.cta.shared::cta.b64 P1, [%0], %1, 0x989680;\n\t" \
            "@P1 bra.uni WD_%=;\n\tbra.uni WL_%=;\n\tWD_%=:\n\t}" \
            :: "r"(_m), "r"(_p) : "memory"); \
    } \
} while (0)
#define BAR_COMPUTE() asm volatile("bar.sync 1, %0;" :: "n"(NCW * 32) : "memory")

__device__ __forceinline__ int expert_of(const int* v, int i) { return d_is64 ? v[2 * i] : v[i]; }

// ======================= K0: detect + reset scratch =======================
__global__ void k0_reset_detect(const int* __restrict__ v32) {
    int i = blockIdx.x * 256 + threadIdx.x;          // 0..8191
    if ((i & 1) && v32[i] != 0) d_is64 = 0;
    for (int j = i; j < MAXTILES * 128; j += 8192) d_perm[j] = -1;
    if (i < MAXTILES * NKC) f_a[i] = 0;
    if (i < NEXP * NNT * NKC) f_b[i] = 0;
    if (i == 0) { f_scat = 0; d_done = 0; }
}

// ======================= K1: per-block hist + global scan =======================
__global__ void k1_hist_scan(const int* __restrict__ v32) {
    __shared__ int h[NEXP];
    const int t = threadIdx.x;
    const int b = blockIdx.x;
    if (t < NEXP) h[t] = 0;
    __syncthreads();
    int e = expert_of(v32, b * 256 + t);
    if (e >= 0 && e < NEXP) atomicAdd(&h[e], 1);
    __syncthreads();
    if (t < NEXP) d_bh[b][t] = h[t];
    __threadfence();
    if (t == 0) {
        int r = atomicAdd(&d_done, 1);
        if (r == NTB - 1) {
            int tot[NEXP];
            for (int ee = 0; ee < NEXP; ee++) {
                int s = 0;
                for (int bb = 0; bb < NTB; bb++) s += d_bh[bb][ee];
                tot[ee] = s;
            }
            int pacc = 0;
            d_poff[0] = 0;
            for (int ee = 0; ee < NEXP; ee++) {
                int base = pacc;
                pacc += ((tot[ee] + 127) / 128) * 128;
                d_poff[ee + 1] = pacc;
                int run = base;
                for (int bb = 0; bb < NTB; bb++) { d_boff[bb][ee] = run; run += d_bh[bb][ee]; }
            }
            d_done = 0;
            __threadfence();
        }
    }
}

// ======================= converter-warp tile conversion =======================
__device__ void convert_b_tile(const float* __restrict__ W, int e, int nt, int kc, int lane) {
    const float* Wb = W + ((size_t)e * DIM + kc * BK) * DIM + nt * BN;
    char* dst = g_wb + ((size_t)((e * NNT + nt) * NKC + kc)) * TILE_B;
    for (int g = lane; g < 4096; g += 32) {
        int k = g >> 5, c = g & 31;
        const float4* s4 = (const float4*)(Wb + (size_t)k * DIM + c * 8);
        float4 w0 = s4[0];
        float4 w1 = s4[1];
        __half2 h0 = __floats2half2_rn(w0.x, w0.y);
        __half2 h1 = __floats2half2_rn(w0.z, w0.w);
        __half2 h2 = __floats2half2_rn(w1.x, w1.y);
        __half2 h3 = __floats2half2_rn(w1.z, w1.w);
        uint4 val;
        val.x = *(uint32_t*)&h0; val.y = *(uint32_t*)&h1;
        val.z = *(uint32_t*)&h2; val.w = *(uint32_t*)&h3;
        *(uint4*)(dst + ((c >> 3) << 14) + sw128((uint32_t)(k * 128 + (c & 7) * 16))) = val;
    }
}
__device__ void convert_a_tile(const float* __restrict__ x, int mt, int kc, int lane) {
    char* dst = g_xa + ((size_t)(mt * NKC + kc)) * TILE_A;
    for (int h = lane; h < 4096; h += 32) {
        int r = h >> 5, Fl = h & 31;
        int grow = d_perm[mt * 128 + r];
        uint2 hv = make_uint2(0u, 0u);
        if (grow >= 0) {
            float4 w = *(const float4*)(x + (size_t)grow * DIM + kc * BK + Fl * 4);
            __half2 h0 = __floats2half2_rn(w.x, w.y);
            __half2 h1 = __floats2half2_rn(w.z, w.w);
            hv.x = *(uint32_t*)&h0; hv.y = *(uint32_t*)&h1;
        }
        *(uint2*)(dst + ((Fl >> 4) << 14) + sw128((uint32_t)(r * 128 + (Fl & 15) * 8))) = hv;
    }
}

// ======================= K2: fused convert + grouped GEMM =======================
__global__ void __launch_bounds__(GTHREADS, 1)
k_mega(const float* __restrict__ x, const float* __restrict__ W,
       const float* __restrict__ bias, float* __restrict__ out,
       const int* __restrict__ v32)
{
    const int nt = blockIdx.x;
    const int mt = blockIdx.y;
    const int bid = mt * NNT + nt;
    const int m0p = mt * BM;
    const bool valid = (m0p < d_poff[NEXP]);

    extern __shared__ char smraw[];
    const uint32_t A0 = (smem_u32(smraw) + 1023u) & ~1023u;
    char* base = smraw + (A0 - smem_u32(smraw));
    const uint32_t mb = A0 + OFF_MB;

    const int tid = threadIdx.x;
    const int wid = tid >> 5;
    const int lane = tid & 31;

    int e = 0;
    if (valid) {
#pragma unroll
        for (int i = 0; i < NEXP; i++) if (m0p >= d_poff[i + 1]) e = i + 1;
    }

    // ================= converter warps =================
    if (wid >= NCW) {
        const int cw = wid - NCW;     // 0..1

        // scatter duty: warp 16 of CTAs bid < NTB
        if (cw == 0 && bid < NTB) {
            short* se = (short*)(base + OFF_SE);
            const int tb = bid;
            for (int i = lane; i < 256; i += 32)
                se[i] = (short)expert_of(v32, tb * 256 + i);
            __syncwarp();
            for (int i = lane; i < 256; i += 32) {
                int ee = se[i];
                int rank = 0;
                for (int j = 0; j < i; j++) rank += (se[j] == (short)ee);
                if (ee >= 0 && ee < NEXP)
                    d_perm[d_boff[tb][ee] + rank] = tb * 256 + i;
            }
            __threadfence();
            __syncwarp();
            if (lane == 0) atomicAdd((int*)&f_scat, 1);
        }
        if (!valid) return;

        // B tiles (no dependency on scatter)
        for (int kc = cw; kc < NKC; kc += 2) {
            volatile int* f = &f_b[(e * NNT + nt) * NKC + kc];
            int old = 0;
            if (lane == 0) old = atomicCAS((int*)f, 0, 1);
            old = __shfl_sync(0xffffffffu, old, 0);
            if (old == 0) {
                convert_b_tile(W, e, nt, kc, lane);
                __threadfence();
                __syncwarp();
                if (lane == 0) *f = 2;
            }
        }
        // wait for scatter, then A tiles
        if (lane == 0) { while (f_scat < NTB) __nanosleep(64); }
        __syncwarp();
        for (int kc = cw; kc < NKC; kc += 2) {
            volatile int* f = &f_a[mt * NKC + kc];
            int old = 0;
            if (lane == 0) old = atomicCAS((int*)f, 0, 1);
            old = __shfl_sync(0xffffffffu, old, 0);
            if (old == 0) {
                convert_a_tile(x, mt, kc, lane);
                __threadfence();
                __syncwarp();
                if (lane == 0) *f = 2;
            }
        }
        return;
    }

    // ================= compute warps =================
    if (!valid) return;
    const int n0 = nt * BN;
    const int warp_m = wid >> 3;     // 0..1 -> 64 m-rows
    const int warp_n = wid & 7;      // 0..7 -> 32 n-cols

    if (tid == 0) {
        MBARRIER_INIT(mb, 1);
        MBARRIER_INIT(mb + 8, 1);
    }
    BAR_COMPUTE();

    // chunk 0: spin flags, issue
    if (tid == 0) {
        while (f_a[mt * NKC + 0] != 2 || f_b[(e * NNT + nt) * NKC + 0] != 2) __nanosleep(64);
        MBARRIER_EXPECT_TX(mb, (uint32_t)STAGE_SZ);
        bulk_g2s(A0, g_xa + (size_t)(mt * NKC) * TILE_A, TILE_A, mb);
        bulk_g2s(A0 + OFF_B, g_wb + (size_t)((e * NNT + nt) * NKC) * TILE_B, TILE_B, mb);
    }

    float acc[4][4][4];
#pragma unroll
    for (int i = 0; i < 4; i++)
#pragma unroll
        for (int j = 0; j < 4; j++)
#pragma unroll
            for (int q = 0; q < 4; q++) acc[i][j][q] = 0.0f;

    const int lrow = lane & 15;
    const int lc16 = (lane >> 4) << 4;
    uint32_t a0off[4];
#pragma unroll
    for (int i = 0; i < 4; i++)
        a0off[i] = sw128((uint32_t)((warp_m * 64 + i * 16 + lrow) * 128 + lc16));

    const int blk = lane >> 3;
    const int ng = blk & 1;
    const int base_k = (blk >> 1) * 8 + (lane & 7);
    uint32_t b0off[2];
#pragma unroll
    for (int g = 0; g < 2; g++) {
        int nn = (warp_n & 1) * 32 + g * 16 + ng * 8;
        b0off[g] = ((uint32_t)(warp_n >> 1) << 14)
                 + sw128((uint32_t)(base_k * 128 + nn * 2));
    }

    for (int c = 0; c < NKC; c++) {
        const int s = c & 1;
        if (tid == 0 && c + 1 < NKC) {
            const int nc = c + 1;
            while (f_a[mt * NKC + nc] != 2 || f_b[(e * NNT + nt) * NKC + nc] != 2) __nanosleep(64);
            uint32_t bar = mb + (nc & 1) * 8;
            MBARRIER_EXPECT_TX(bar, (uint32_t)STAGE_SZ);
            uint32_t sb = A0 + (nc & 1) * STAGE_SZ;
            bulk_g2s(sb, g_xa + (size_t)(mt * NKC + nc) * TILE_A, TILE_A, bar);
            bulk_g2s(sb + OFF_B, g_wb + (size_t)((e * NNT + nt) * NKC + nc) * TILE_B, TILE_B, bar);
        }

        MBARRIER_WAIT_PARITY(mb + s * 8, (c >> 1) & 1);

        const uint32_t aA = A0 + s * STAGE_SZ;
        const uint32_t aB = aA + OFF_B;
#pragma unroll
        for (int ks = 0; ks < 8; ks++) {
            uint32_t bf[2][4];
            const uint32_t bofs = aB + ((uint32_t)ks << 11);
#pragma unroll
            for (int g = 0; g < 2; g++) ldsm_x4_t(bf[g], bofs + b0off[g]);
            const uint32_t asub = aA + ((uint32_t)(ks >> 2) << 14);
            const uint32_t akx = (uint32_t)((ks & 3) << 5);
#pragma unroll
            for (int i = 0; i < 4; i++) {
                uint32_t af[4];
                ldsm_x4(af, asub + (a0off[i] ^ akx));
#pragma unroll
                for (int j = 0; j < 4; j++)
                    mma16816(acc[i][j], af, bf[j >> 1][j & 1], bf[j >> 1][(j & 1) + 2]);
            }
        }
        BAR_COMPUTE();
    }

    // epilogue: rows load (safe: flags==2 implies scatter complete), bias, scatter out
    int* rows = (int*)(base + OFF_ROWS);
    if (tid < BM) rows[tid] = d_perm[m0p + tid];
    BAR_COMPUTE();

    const float* be = bias + (size_t)e * DIM;
#pragma unroll
    for (int i = 0; i < 4; i++) {
#pragma unroll
        for (int half = 0; half < 2; half++) {
            int mloc = warp_m * 64 + i * 16 + (lane >> 2) + half * 8;
            int grow = rows[mloc];
            if (grow < 0) continue;
            float* orow = out + (size_t)grow * DIM;
#pragma unroll
            for (int j = 0; j < 4; j++) {
                int col = n0 + warp_n * 32 + j * 8 + (lane & 3) * 2;
                float2 bb = *(const float2*)(be + col);
                float2 o;
                o.x = acc[i][j][half * 2 + 0] + bb.x;
                o.y = acc[i][j][half * 2 + 1] + bb.y;
                *(float2*)(orow + col) = o;
            }
        }
    }
}

// ======================= host =======================
extern "C" void kernel_launch(void* const* d_in, const int* in_sizes, int n_in,
                              void* d_out, int out_size)
{
    const float* x = nullptr;
    const float* W = nullptr;
    const float* b = nullptr;
    const void* idx = nullptr;
    for (int i = 0; i < n_in; i++) {
        long long sz = in_sizes[i];
        if      (sz == (long long)B_TOK * DIM)      x = (const float*)d_in[i];
        else if (sz == (long long)NEXP * DIM * DIM) W = (const float*)d_in[i];
        else if (sz == (long long)NEXP * DIM)       b = (const float*)d_in[i];
        else if (sz == (long long)B_TOK)            idx = d_in[i];
    }
    float* out = (float*)d_out;
    const int* v32 = (const int*)idx;

    cudaFuncSetAttribute(k_mega, cudaFuncAttributeMaxDynamicSharedMemorySize, SMEM_REQ);

    k0_reset_detect<<<32, 256>>>(v32);                 // launch 1
    k1_hist_scan<<<NTB, 256>>>(v32);                   // launch 2
    dim3 ggrid(NNT, MAXTILES);
    k_mega<<<ggrid, GTHREADS, SMEM_REQ>>>(x, W, b, out, v32);  // launch 3
}

// round 11
// speedup vs baseline: 1.5438x; 1.5438x over previous
#include <cuda_runtime.h>
#include <cuda_fp16.h>
#include <stdint.h>

#define B_TOK 8192
#define DIM   2048
#define NEXP  8

#define BM 128
#define BN 128
#define BK 128
#define NKC (DIM / BK)          // 16
#define NNT (DIM / BN)          // 16
#define MAXTILES 72
#define GTHREADS 256            // 8 compute warps

// dynamic smem: 2 stages x (A fp16 32KB + B fp16 32KB)
#define TILE_A 32768
#define STAGE_SZ 65536
#define OFF_B TILE_A
#define SMEM_REQ (2 * STAGE_SZ + 1024)

#define NTB 32

// -------- device scratch --------
__device__ int d_bh[NTB][NEXP];
__device__ int d_boff[NTB][NEXP];
__device__ int d_poff[NEXP + 1];
__device__ int d_is64 = 1;           // monotone latch
__device__ int d_done = 0;
__device__ int d_perm[MAXTILES * 128];

// ======================= helpers =======================
__device__ __forceinline__ uint32_t smem_u32(const void* p) {
    uint32_t a;
    asm("{ .reg .u64 t; cvta.to.shared.u64 t, %1; cvt.u32.u64 %0, t; }" : "=r"(a) : "l"(p));
    return a;
}
__device__ __forceinline__ uint32_t sw128(uint32_t off) { return off ^ ((off >> 3) & 0x70); }

__device__ __forceinline__ void ldsm_x4(uint32_t* r, uint32_t addr) {
    asm volatile("ldmatrix.sync.aligned.m8n8.x4.shared.b16 {%0,%1,%2,%3}, [%4];"
                 : "=r"(r[0]), "=r"(r[1]), "=r"(r[2]), "=r"(r[3]) : "r"(addr));
}
__device__ __forceinline__ void ldsm_x4_t(uint32_t* r, uint32_t addr) {
    asm volatile("ldmatrix.sync.aligned.m8n8.x4.trans.shared.b16 {%0,%1,%2,%3}, [%4];"
                 : "=r"(r[0]), "=r"(r[1]), "=r"(r[2]), "=r"(r[3]) : "r"(addr));
}
__device__ __forceinline__ void mma16816(float* d, const uint32_t* a, uint32_t b0, uint32_t b1) {
    asm volatile(
        "mma.sync.aligned.m16n8k16.row.col.f32.f16.f16.f32 "
        "{%0,%1,%2,%3}, {%4,%5,%6,%7}, {%8,%9}, {%0,%1,%2,%3};"
        : "+f"(d[0]), "+f"(d[1]), "+f"(d[2]), "+f"(d[3])
        : "r"(a[0]), "r"(a[1]), "r"(a[2]), "r"(a[3]), "r"(b0), "r"(b1));
}
__device__ __forceinline__ int expert_of(const int* v, int i) { return d_is64 ? v[2 * i] : v[i]; }

// ======================= K0: detect + reset =======================
__global__ void k0_reset_detect(const int* __restrict__ v32) {
    int i = blockIdx.x * 256 + threadIdx.x;          // 0..8191
    if ((i & 1) && v32[i] != 0) d_is64 = 0;
    for (int j = i; j < MAXTILES * 128; j += 8192) d_perm[j] = -1;
    if (i == 0) d_done = 0;
}

// ======================= K1: per-block hist + global scan =======================
__global__ void k1_hist_scan(const int* __restrict__ v32) {
    __shared__ int h[NEXP];
    const int t = threadIdx.x;
    const int b = blockIdx.x;
    if (t < NEXP) h[t] = 0;
    __syncthreads();
    int e = expert_of(v32, b * 256 + t);
    if (e >= 0 && e < NEXP) atomicAdd(&h[e], 1);
    __syncthreads();
    if (t < NEXP) d_bh[b][t] = h[t];
    __threadfence();
    if (t == 0) {
        int r = atomicAdd(&d_done, 1);
        if (r == NTB - 1) {
            int tot[NEXP];
            for (int ee = 0; ee < NEXP; ee++) {
                int s = 0;
                for (int bb = 0; bb < NTB; bb++) s += d_bh[bb][ee];
                tot[ee] = s;
            }
            int pacc = 0;
            d_poff[0] = 0;
            for (int ee = 0; ee < NEXP; ee++) {
                int base = pacc;
                pacc += ((tot[ee] + 127) / 128) * 128;
                d_poff[ee + 1] = pacc;
                int run = base;
                for (int bb = 0; bb < NTB; bb++) { d_boff[bb][ee] = run; run += d_bh[bb][ee]; }
            }
            d_done = 0;
            __threadfence();
        }
    }
}

// ======================= K2: deterministic scatter =======================
__global__ void k2_scatter(const int* __restrict__ v32) {
    __shared__ short se[256];
    const int t = threadIdx.x;
    const int tb = blockIdx.x;
    int e = expert_of(v32, tb * 256 + t);
    se[t] = (short)e;
    __syncthreads();
    int rank = 0;
    for (int j = 0; j < t; j++) rank += (se[j] == (short)e);
    if (e >= 0 && e < NEXP)
        d_perm[d_boff[tb][e] + rank] = tb * 256 + t;
}

// ======================= K3: fused convert + grouped GEMM =======================
// Per chunk (fp32 -> fp16, SW128-swizzled, written by compute threads):
//   A: gathered x rows [128m x 128k], 2 k-subtiles of (128m x 64k)
//   B: W rows [128k x 128n] (K-major, n contiguous), 2 n-subtiles of (128k x 64n)

__global__ void __launch_bounds__(GTHREADS, 1)
k_gemm(const float* __restrict__ x, const float* __restrict__ W,
       const float* __restrict__ bias, float* __restrict__ out)
{
    const int nt = blockIdx.x;
    const int mt = blockIdx.y;
    const int m0p = mt * BM;
    if (m0p >= d_poff[NEXP]) return;
    int e = 0;
#pragma unroll
    for (int i = 0; i < NEXP; i++) if (m0p >= d_poff[i + 1]) e = i + 1;
    const int n0 = nt * BN;

    extern __shared__ char smraw[];
    const uint32_t A0 = (smem_u32(smraw) + 1023u) & ~1023u;
    char* sbase = smraw + (A0 - smem_u32(smraw));

    __shared__ int rows[BM];

    const int tid = threadIdx.x;
    const int wid = tid >> 5;
    const int lane = tid & 31;
    const int warp_m = wid >> 2;     // 0..1 -> 64 m-rows
    const int warp_n = wid & 3;      // 0..3 -> 32 n-cols

    if (tid < BM) rows[tid] = d_perm[m0p + tid];
    __syncthreads();

    // per-thread fixed granule coords: g = i*256 + tid, r|k = g>>5, c = g&31
    const int c0 = tid & 31;                 // column granule (same every i)
    const int r0 = tid >> 5;                 // row offset within 8-row group
    const float* Wb = W + (size_t)e * DIM * DIM + n0;

    // ---------- chunk 0 conversion ----------
    {
        char* dA = sbase;            // stage 0 A
        char* dB = sbase + OFF_B;    // stage 0 B
#pragma unroll
        for (int i = 0; i < 16; i++) {
            int r = i * 8 + r0;
            int grow = rows[r];
            uint4 ua = make_uint4(0u, 0u, 0u, 0u);
            if (grow >= 0) ua = *(const uint4*)(x + (size_t)grow * DIM + c0 * 4);
            float4 w = *(const float4*)&ua;
            __half2 h0 = __floats2half2_rn(w.x, w.y);
            __half2 h1 = __floats2half2_rn(w.z, w.w);
            uint2 hv; hv.x = *(uint32_t*)&h0; hv.y = *(uint32_t*)&h1;
            *(uint2*)(dA + ((c0 >> 4) << 14) + sw128((uint32_t)(r * 128 + (c0 & 15) * 8))) = hv;

            uint4 ub = *(const uint4*)(Wb + (size_t)r * DIM + c0 * 4);
            // note: B rows are k-rows; for chunk 0, k = i*8+r0 = r
            float4 v = *(const float4*)&ub;
            __half2 g0 = __floats2half2_rn(v.x, v.y);
            __half2 g1 = __floats2half2_rn(v.z, v.w);
            uint2 gv; gv.x = *(uint32_t*)&g0; gv.y = *(uint32_t*)&g1;
            *(uint2*)(dB + ((c0 >> 4) << 14) + sw128((uint32_t)(r * 128 + (c0 & 15) * 8))) = gv;
        }
    }
    __syncthreads();

    float acc[4][4][4];
#pragma unroll
    for (int i = 0; i < 4; i++)
#pragma unroll
        for (int j = 0; j < 4; j++)
#pragma unroll
            for (int q = 0; q < 4; q++) acc[i][j][q] = 0.0f;

    // ldsm fragment base offsets (round-9 verified mapping, BN=128)
    const int lrow = lane & 15;
    const int lc16 = (lane >> 4) << 4;
    uint32_t a0off[4];
#pragma unroll
    for (int i = 0; i < 4; i++)
        a0off[i] = sw128((uint32_t)((warp_m * 64 + i * 16 + lrow) * 128 + lc16));
    const int blk = lane >> 3;
    const int ng = blk & 1;
    const int base_k = (blk >> 1) * 8 + (lane & 7);
    uint32_t b0off[2];
#pragma unroll
    for (int g = 0; g < 2; g++) {
        int nn = (warp_n & 1) * 32 + g * 16 + ng * 8;
        b0off[g] = ((uint32_t)(warp_n >> 1) << 14)
                 + sw128((uint32_t)(base_k * 128 + nn * 2));
    }
    // precomputed STS destination offset (same for A and B tiles, per thread per i)
    const uint32_t sts_sub = ((uint32_t)(c0 >> 4) << 14);

    for (int c = 0; c < NKC; c++) {
        const int s = c & 1;
        const uint32_t aA = A0 + s * STAGE_SZ;
        const uint32_t aB = aA + OFF_B;
        char* dA = sbase + (s ^ 1) * STAGE_SZ;
        char* dB = dA + OFF_B;
        const bool more = (c + 1 < NKC);
        const int nk0 = (c + 1) * BK;        // next chunk k base

        // ---- load next A batch (held in regs across first MMA half) ----
        uint4 ra[16];
        if (more) {
#pragma unroll
            for (int i = 0; i < 16; i++) {
                int r = i * 8 + r0;
                int grow = rows[r];
                ra[i] = make_uint4(0u, 0u, 0u, 0u);
                if (grow >= 0)
                    ra[i] = *(const uint4*)(x + (size_t)grow * DIM + nk0 + c0 * 4);
            }
        }

        // ---- MMA ks 0..3 ----
#pragma unroll
        for (int ks = 0; ks < 4; ks++) {
            uint32_t bf[2][4];
            const uint32_t bofs = aB + ((uint32_t)ks << 11);
#pragma unroll
            for (int g = 0; g < 2; g++) ldsm_x4_t(bf[g], bofs + b0off[g]);
            const uint32_t akx = (uint32_t)(ks << 5);
#pragma unroll
            for (int i = 0; i < 4; i++) {
                uint32_t af[4];
                ldsm_x4(af, aA + (a0off[i] ^ akx));
#pragma unroll
                for (int j = 0; j < 4; j++)
                    mma16816(acc[i][j], af, bf[j >> 1][j & 1], bf[j >> 1][(j & 1) + 2]);
            }
        }

        // ---- store next A, load next B ----
        uint4 rb[16];
        if (more) {
#pragma unroll
            for (int i = 0; i < 16; i++) {
                int r = i * 8 + r0;
                float4 w = *(const float4*)&ra[i];
                __half2 h0 = __floats2half2_rn(w.x, w.y);
                __half2 h1 = __floats2half2_rn(w.z, w.w);
                uint2 hv; hv.x = *(uint32_t*)&h0; hv.y = *(uint32_t*)&h1;
                *(uint2*)(dA + sts_sub + sw128((uint32_t)(r * 128 + (c0 & 15) * 8))) = hv;
            }
#pragma unroll
            for (int i = 0; i < 16; i++) {
                int k = i * 8 + r0;
                rb[i] = *(const uint4*)(Wb + (size_t)(nk0 + k) * DIM + c0 * 4);
            }
        }

        // ---- MMA ks 4..7 ----
#pragma unroll
        for (int ks = 4; ks < 8; ks++) {
            uint32_t bf[2][4];
            const uint32_t bofs = aB + ((uint32_t)ks << 11);
#pragma unroll
            for (int g = 0; g < 2; g++) ldsm_x4_t(bf[g], bofs + b0off[g]);
            const uint32_t asub = aA + 16384;
            const uint32_t akx = (uint32_t)((ks & 3) << 5);
#pragma unroll
            for (int i = 0; i < 4; i++) {
                uint32_t af[4];
                ldsm_x4(af, asub + (a0off[i] ^ akx));
#pragma unroll
                for (int j = 0; j < 4; j++)
                    mma16816(acc[i][j], af, bf[j >> 1][j & 1], bf[j >> 1][(j & 1) + 2]);
            }
        }

        // ---- store next B ----
        if (more) {
#pragma unroll
            for (int i = 0; i < 16; i++) {
                int k = i * 8 + r0;
                float4 v = *(const float4*)&rb[i];
                __half2 g0 = __floats2half2_rn(v.x, v.y);
                __half2 g1 = __floats2half2_rn(v.z, v.w);
                uint2 gv; gv.x = *(uint32_t*)&g0; gv.y = *(uint32_t*)&g1;
                *(uint2*)(dB + sts_sub + sw128((uint32_t)(k * 128 + (c0 & 15) * 8))) = gv;
            }
        }
        __syncthreads();
    }

    // note on B k-subtiles: ks<4 reads k rows 0..63 from dB base; ks>=4 reads rows 64..127.
    // B tile layout above is a single 128k x (2 n-subtiles x 64n) region where row k lives at
    // k*128 within its n-subtile -- rows 64..127 offsets 8192..16255 stay inside the 16KB
    // subtile, so bofs = aB + ks*2048 covers them contiguously. (identical to round-9 layout)

    // epilogue: add bias, scatter rows
    const float* be = bias + (size_t)e * DIM;
#pragma unroll
    for (int i = 0; i < 4; i++) {
#pragma unroll
        for (int half = 0; half < 2; half++) {
            int mloc = warp_m * 64 + i * 16 + (lane >> 2) + half * 8;
            int grow = rows[mloc];
            if (grow < 0) continue;
            float* orow = out + (size_t)grow * DIM;
#pragma unroll
            for (int j = 0; j < 4; j++) {
                int col = n0 + warp_n * 32 + j * 8 + (lane & 3) * 2;
                float2 bb = *(const float2*)(be + col);
                float2 o;
                o.x = acc[i][j][half * 2 + 0] + bb.x;
                o.y = acc[i][j][half * 2 + 1] + bb.y;
                *(float2*)(orow + col) = o;
            }
        }
    }
}

// ======================= host =======================
extern "C" void kernel_launch(void* const* d_in, const int* in_sizes, int n_in,
                              void* d_out, int out_size)
{
    const float* x = nullptr;
    const float* W = nullptr;
    const float* b = nullptr;
    const void* idx = nullptr;
    for (int i = 0; i < n_in; i++) {
        long long sz = in_sizes[i];
        if      (sz == (long long)B_TOK * DIM)      x = (const float*)d_in[i];
        else if (sz == (long long)NEXP * DIM * DIM) W = (const float*)d_in[i];
        else if (sz == (long long)NEXP * DIM)       b = (const float*)d_in[i];
        else if (sz == (long long)B_TOK)            idx = d_in[i];
    }
    float* out = (float*)d_out;
    const int* v32 = (const int*)idx;

    cudaFuncSetAttribute(k_gemm, cudaFuncAttributeMaxDynamicSharedMemorySize, SMEM_REQ);

    k0_reset_detect<<<32, 256>>>(v32);               // launch 1
    k1_hist_scan<<<NTB, 256>>>(v32);                 // launch 2
    k2_scatter<<<NTB, 256>>>(v32);                   // launch 3
    dim3 ggrid(NNT, MAXTILES);                       // (16, 72)
    k_gemm<<<ggrid, GTHREADS, SMEM_REQ>>>(x, W, b, out);  // launch 4 (ncu target)
}